// round 13
// baseline (speedup 1.0000x reference)
#include <cuda_runtime.h>
#include <math_constants.h>

// DarkChannel fused (R4 champion, __stcs regression reverted):
//   phase 1: channel-min(C=3) + vertical 15-min van Herk (float2/thread) -> smem
//   phase 2: horizontal 15-min from smem (5x LDS.128 per 4 outputs) -> out
//   interior fast path in phase 2; normal write-back stores.
//
// img [16,3,1024,1024] f32 -> out [16,1,1024,1024] f32, +inf border erosion.

#define IMG_H 1024
#define IMG_W 1024
#define IMG_B 16
#define CH_STRIDE (IMG_H * IMG_W)
#define YTILE 15
#define NUM_TY 69
#define XSPAN 512
#define HALO 8
#define SROW (XSPAN + 2 * HALO)          // 528
#define NTHREADS 288                     // 264 active in phase 1

__device__ __forceinline__ float2 min2(float2 a, float2 b) {
    return make_float2(fminf(a.x, b.x), fminf(a.y, b.y));
}

template <bool CHECKY>
__device__ __forceinline__ float2 cmin2(const float* p, int y, bool vx) {
    if (!vx || (CHECKY && (unsigned)y >= (unsigned)IMG_H)) {
        return make_float2(CUDART_INF_F, CUDART_INF_F);
    }
    const float* r = p + (size_t)y * IMG_W;
    float2 c0 = *reinterpret_cast<const float2*>(r);
    float2 c1 = *reinterpret_cast<const float2*>(r + CH_STRIDE);
    float2 c2 = *reinterpret_cast<const float2*>(r + 2 * CH_STRIDE);
    return min2(min2(c0, c1), c2);
}

// Vertical van Herk (window == block == 15) for one float2 column pair.
template <bool CHECKY>
__device__ __forceinline__ void vert(const float* p, bool vx, int y0, float* s) {
    float2 h[YTILE];
#pragma unroll
    for (int t = 0; t < YTILE; ++t) {
        h[t] = cmin2<CHECKY>(p, y0 - 7 + t, vx);        // rows y0-7 .. y0+7
    }
#pragma unroll
    for (int t = YTILE - 2; t >= 0; --t) {
        h[t] = min2(h[t], h[t + 1]);                    // suffix mins
    }

    *reinterpret_cast<float2*>(&s[0]) = h[0];

    float2 g = make_float2(CUDART_INF_F, CUDART_INF_F);
#pragma unroll
    for (int r = 1; r < YTILE; ++r) {
        g = min2(g, cmin2<CHECKY>(p, y0 + 7 + r, vx));  // next-block prefix
        *reinterpret_cast<float2*>(&s[r * SROW]) = min2(h[r], g);
    }
}

// One horizontal 15-min group: 4 outputs from 20 smem floats.
__device__ __forceinline__ void hgroup(const float* row, int L0, float* op) {
    float f[20];
#pragma unroll
    for (int q = 0; q < 5; ++q) {
        float4 v = *reinterpret_cast<const float4*>(&row[L0 - 8 + 4 * q]);
        f[q * 4 + 0] = v.x;
        f[q * 4 + 1] = v.y;
        f[q * 4 + 2] = v.z;
        f[q * 4 + 3] = v.w;
    }

    float core = f[4];
#pragma unroll
    for (int k = 5; k <= 15; ++k) core = fminf(core, f[k]);

    float p23   = fminf(f[2], f[3]);
    float p1617 = fminf(f[16], f[17]);

    float4 o;
    o.x = fminf(core, fminf(f[1], p23));
    o.y = fminf(core, fminf(p23, f[16]));
    o.z = fminf(core, fminf(f[3], p1617));
    o.w = fminf(core, fminf(p1617, f[18]));

    *reinterpret_cast<float4*>(op) = o;                 // normal write-back store
}

extern "C" __global__ __launch_bounds__(NTHREADS, 4)
void k_fused(const float* __restrict__ img, float* __restrict__ out) {
    __shared__ float sV[YTILE * SROW];                  // 31680 B

    const int tid = threadIdx.x;
    const int bx  = blockIdx.x;                         // x strip 0..1
    const int ty  = blockIdx.y;                         // y tile 0..68
    const int b   = blockIdx.z;
    const int y0  = ty * YTILE;
    const int X0  = bx * XSPAN;

    // ---- Phase 1: vertical erosion of SROW cols (incl. +/-8 halo) ----
    if (tid < SROW / 2) {                               // 264 active
        const int lc = tid << 1;
        const int gx = X0 - HALO + lc;
        const bool vx = (unsigned)gx < (unsigned)IMG_W;
        const float* p = img + (size_t)b * 3 * CH_STRIDE + gx;
        if (ty >= 1 && ty <= 66) {
            vert<false>(p, vx, y0, &sV[lc]);
        } else {
            vert<true>(p, vx, y0, &sV[lc]);
        }
    }

    __syncthreads();

    // ---- Phase 2: horizontal 15-min from smem ----
    float* outb = out + (size_t)b * IMG_H * IMG_W;

    if (ty != NUM_TY - 1) {
        // interior: all 15 rows valid; 128*15 = 1920 quads
#pragma unroll 1
        for (int i = tid; i < (XSPAN / 4) * YTILE; i += NTHREADS) {
            const int r = i >> 7;
            const int c = i & 127;
            hgroup(&sV[r * SROW], (c << 2) + HALO,
                   outb + (size_t)(y0 + r) * IMG_W + X0 + (c << 2));
        }
    } else {
        const int vrows = IMG_H - y0;                   // last tile: 4 rows
#pragma unroll 1
        for (int i = tid; i < (XSPAN / 4) * vrows; i += NTHREADS) {
            const int r = i >> 7;
            const int c = i & 127;
            hgroup(&sV[r * SROW], (c << 2) + HALO,
                   outb + (size_t)(y0 + r) * IMG_W + X0 + (c << 2));
        }
    }
}

extern "C" void kernel_launch(void* const* d_in, const int* in_sizes, int n_in,
                              void* d_out, int out_size) {
    const float* img = (const float*)d_in[0];
    float* out = (float*)d_out;

    static bool attr_set = false;
    if (!attr_set) {
        // Keep carveout at the minimum that still fits 4 blocks (4 x 31.7 KB),
        // leaving the rest of unified L1 as data cache for halo rereads.
        cudaFuncSetAttribute(k_fused,
                             cudaFuncAttributePreferredSharedMemoryCarveout, 56);
        attr_set = true;
    }

    dim3 grid(IMG_W / XSPAN, NUM_TY, IMG_B);            // 2 x 69 x 16
    k_fused<<<grid, NTHREADS>>>(img, out);
}

// round 14
// speedup vs baseline: 1.0358x; 1.0358x over previous
#include <cuda_runtime.h>
#include <math_constants.h>

// DarkChannel fused (exact R4 champion — best measured config of the session):
//   phase 1: channel-min(C=3) + vertical 15-min van Herk (float2/thread) -> smem
//   phase 2: horizontal 15-min from smem (5x LDS.128 per 4 outputs) -> out
//
// img [16,3,1024,1024] f32 -> out [16,1,1024,1024] f32, +inf border erosion.

#define IMG_H 1024
#define IMG_W 1024
#define IMG_B 16
#define CH_STRIDE (IMG_H * IMG_W)
#define YTILE 15
#define XSPAN 512
#define HALO 8
#define SROW (XSPAN + 2 * HALO)          // 528
#define NTHREADS 288

__device__ __forceinline__ float2 min2(float2 a, float2 b) {
    return make_float2(fminf(a.x, b.x), fminf(a.y, b.y));
}

template <bool CHECKY>
__device__ __forceinline__ float2 cmin2(const float* p, int y, bool vx) {
    if (!vx || (CHECKY && (unsigned)y >= (unsigned)IMG_H)) {
        return make_float2(CUDART_INF_F, CUDART_INF_F);
    }
    const float* r = p + (size_t)y * IMG_W;
    float2 c0 = *reinterpret_cast<const float2*>(r);
    float2 c1 = *reinterpret_cast<const float2*>(r + CH_STRIDE);
    float2 c2 = *reinterpret_cast<const float2*>(r + 2 * CH_STRIDE);
    return min2(min2(c0, c1), c2);
}

// Vertical van Herk, block size == window == 15. Writes 15 rows into smem
// column slot s (stride SROW floats between rows).
template <bool CHECKY>
__device__ __forceinline__ void vert(const float* p, bool vx, int y0, float* s) {
    float2 h[YTILE];
#pragma unroll
    for (int t = 0; t < YTILE; ++t) {
        h[t] = cmin2<CHECKY>(p, y0 - 7 + t, vx);     // rows y0-7 .. y0+7
    }
#pragma unroll
    for (int t = YTILE - 2; t >= 0; --t) {
        h[t] = min2(h[t], h[t + 1]);                 // suffix mins
    }

    *reinterpret_cast<float2*>(&s[0]) = h[0];

    float2 g = make_float2(CUDART_INF_F, CUDART_INF_F);
#pragma unroll
    for (int r = 1; r < YTILE; ++r) {
        g = min2(g, cmin2<CHECKY>(p, y0 + 7 + r, vx));   // next-block prefix
        *reinterpret_cast<float2*>(&s[r * SROW]) = min2(h[r], g);
    }
}

extern "C" __global__ __launch_bounds__(NTHREADS, 4)
void k_fused(const float* __restrict__ img, float* __restrict__ out) {
    __shared__ float sV[YTILE * SROW];               // 31680 B static

    const int tid = threadIdx.x;
    const int bx  = blockIdx.x;                      // 0..1  (x tile)
    const int ty  = blockIdx.y;                      // 0..68 (y tile)
    const int b   = blockIdx.z;
    const int y0  = ty * YTILE;
    const int X0  = bx * XSPAN;

    // ---- Phase 1: vertical erosion of 528 cols (incl. +/-8 halo) ----
    {
        const int lc = tid << 1;                     // local col pair
        if (lc < SROW) {                             // threads 0..263
            const int gx = X0 - HALO + lc;
            const bool vx = (unsigned)gx < (unsigned)IMG_W;
            const float* p = img + (size_t)b * 3 * CH_STRIDE + gx;
            if (ty >= 1 && ty <= 66) {
                vert<false>(p, vx, y0, &sV[lc]);     // interior in y
            } else {
                vert<true>(p, vx, y0, &sV[lc]);
            }
        }
    }

    __syncthreads();

    // ---- Phase 2: horizontal 15-min from smem (no bounds checks) ----
    const int vrows = min(YTILE, IMG_H - y0);
    const int nquads = 128 * YTILE;                  // 128 float4 per row

    for (int i = tid; i < nquads; i += NTHREADS) {
        const int r = i >> 7;
        if (r >= vrows) break;                       // r nondecreasing in i
        const int c = i & 127;

        const float* row = &sV[r * SROW];
        const int L0 = (c << 2) + HALO;              // local col of first output

        float f[20];
#pragma unroll
        for (int q = 0; q < 5; ++q) {
            float4 v = *reinterpret_cast<const float4*>(&row[L0 - 8 + 4 * q]);
            f[q * 4 + 0] = v.x;
            f[q * 4 + 1] = v.y;
            f[q * 4 + 2] = v.z;
            f[q * 4 + 3] = v.w;
        }

        float core = f[4];
#pragma unroll
        for (int k = 5; k <= 15; ++k) core = fminf(core, f[k]);

        float p23   = fminf(f[2], f[3]);
        float p1617 = fminf(f[16], f[17]);

        float4 o;
        o.x = fminf(core, fminf(f[1], p23));
        o.y = fminf(core, fminf(p23, f[16]));
        o.z = fminf(core, fminf(f[3], p1617));
        o.w = fminf(core, fminf(p1617, f[18]));

        float* op = out + ((size_t)b * IMG_H + y0 + r) * IMG_W + X0 + (c << 2);
        *reinterpret_cast<float4*>(op) = o;
    }
}

extern "C" void kernel_launch(void* const* d_in, const int* in_sizes, int n_in,
                              void* d_out, int out_size) {
    const float* img = (const float*)d_in[0];
    float* out = (float*)d_out;

    dim3 grid(IMG_W / XSPAN, (IMG_H + YTILE - 1) / YTILE, IMG_B);   // 2 x 69 x 16
    k_fused<<<grid, NTHREADS>>>(img, out);
}

// round 15
// speedup vs baseline: 1.0562x; 1.0197x over previous
#include <cuda_runtime.h>
#include <math_constants.h>

// DarkChannel fused (R4 champion + batched streaming loads for higher MLP):
//   phase 1: channel-min(C=3) + vertical 15-min van Herk (float2/thread).
//            Rows y0-7..y0+7 front-batched (45 LDG), then the 14 prefix rows
//            in two batches of 7 (21 independent LDGs each) instead of a
//            3-load-at-a-time streaming loop.
//   phase 2: horizontal 15-min from smem (5x LDS.128 per 4 outputs) -> out
//
// img [16,3,1024,1024] f32 -> out [16,1,1024,1024] f32, +inf border erosion.

#define IMG_H 1024
#define IMG_W 1024
#define IMG_B 16
#define CH_STRIDE (IMG_H * IMG_W)
#define YTILE 15
#define XSPAN 512
#define HALO 8
#define SROW (XSPAN + 2 * HALO)          // 528
#define NTHREADS 288

__device__ __forceinline__ float2 min2(float2 a, float2 b) {
    return make_float2(fminf(a.x, b.x), fminf(a.y, b.y));
}

template <bool CHECKY>
__device__ __forceinline__ float2 cmin2(const float* p, int y, bool vx) {
    if (!vx || (CHECKY && (unsigned)y >= (unsigned)IMG_H)) {
        return make_float2(CUDART_INF_F, CUDART_INF_F);
    }
    const float* r = p + (size_t)y * IMG_W;
    float2 c0 = *reinterpret_cast<const float2*>(r);
    float2 c1 = *reinterpret_cast<const float2*>(r + CH_STRIDE);
    float2 c2 = *reinterpret_cast<const float2*>(r + 2 * CH_STRIDE);
    return min2(min2(c0, c1), c2);
}

// Vertical van Herk (window == block == 15), prefix rows in two 7-row batches.
template <bool CHECKY>
__device__ __forceinline__ void vert(const float* p, bool vx, int y0, float* s) {
    float2 h[YTILE];
#pragma unroll
    for (int t = 0; t < YTILE; ++t) {
        h[t] = cmin2<CHECKY>(p, y0 - 7 + t, vx);     // rows y0-7 .. y0+7
    }
#pragma unroll
    for (int t = YTILE - 2; t >= 0; --t) {
        h[t] = min2(h[t], h[t + 1]);                 // suffix mins
    }

    *reinterpret_cast<float2*>(&s[0]) = h[0];

    float2 g = make_float2(CUDART_INF_F, CUDART_INF_F);

    // batch A: rows y0+8 .. y0+14  (outputs r = 1..7)
    {
        float2 m[7];
#pragma unroll
        for (int j = 0; j < 7; ++j) {
            m[j] = cmin2<CHECKY>(p, y0 + 8 + j, vx); // 21 independent LDGs
        }
#pragma unroll
        for (int r = 1; r <= 7; ++r) {
            g = min2(g, m[r - 1]);
            *reinterpret_cast<float2*>(&s[r * SROW]) = min2(h[r], g);
        }
    }

    // batch B: rows y0+15 .. y0+21  (outputs r = 8..14)
    {
        float2 m[7];
#pragma unroll
        for (int j = 0; j < 7; ++j) {
            m[j] = cmin2<CHECKY>(p, y0 + 15 + j, vx);
        }
#pragma unroll
        for (int r = 8; r <= 14; ++r) {
            g = min2(g, m[r - 8]);
            *reinterpret_cast<float2*>(&s[r * SROW]) = min2(h[r], g);
        }
    }
}

extern "C" __global__ __launch_bounds__(NTHREADS, 3)
void k_fused(const float* __restrict__ img, float* __restrict__ out) {
    __shared__ float sV[YTILE * SROW];               // 31680 B static

    const int tid = threadIdx.x;
    const int bx  = blockIdx.x;                      // 0..1  (x tile)
    const int ty  = blockIdx.y;                      // 0..68 (y tile)
    const int b   = blockIdx.z;
    const int y0  = ty * YTILE;
    const int X0  = bx * XSPAN;

    // ---- Phase 1: vertical erosion of 528 cols (incl. +/-8 halo) ----
    {
        const int lc = tid << 1;                     // local col pair
        if (lc < SROW) {                             // threads 0..263
            const int gx = X0 - HALO + lc;
            const bool vx = (unsigned)gx < (unsigned)IMG_W;
            const float* p = img + (size_t)b * 3 * CH_STRIDE + gx;
            if (ty >= 1 && ty <= 66) {
                vert<false>(p, vx, y0, &sV[lc]);     // interior in y
            } else {
                vert<true>(p, vx, y0, &sV[lc]);
            }
        }
    }

    __syncthreads();

    // ---- Phase 2: horizontal 15-min from smem (no bounds checks) ----
    const int vrows = min(YTILE, IMG_H - y0);
    const int nquads = 128 * YTILE;                  // 128 float4 per row

    for (int i = tid; i < nquads; i += NTHREADS) {
        const int r = i >> 7;
        if (r >= vrows) break;                       // r nondecreasing in i
        const int c = i & 127;

        const float* row = &sV[r * SROW];
        const int L0 = (c << 2) + HALO;              // local col of first output

        float f[20];
#pragma unroll
        for (int q = 0; q < 5; ++q) {
            float4 v = *reinterpret_cast<const float4*>(&row[L0 - 8 + 4 * q]);
            f[q * 4 + 0] = v.x;
            f[q * 4 + 1] = v.y;
            f[q * 4 + 2] = v.z;
            f[q * 4 + 3] = v.w;
        }

        float core = f[4];
#pragma unroll
        for (int k = 5; k <= 15; ++k) core = fminf(core, f[k]);

        float p23   = fminf(f[2], f[3]);
        float p1617 = fminf(f[16], f[17]);

        float4 o;
        o.x = fminf(core, fminf(f[1], p23));
        o.y = fminf(core, fminf(p23, f[16]));
        o.z = fminf(core, fminf(f[3], p1617));
        o.w = fminf(core, fminf(p1617, f[18]));

        float* op = out + ((size_t)b * IMG_H + y0 + r) * IMG_W + X0 + (c << 2);
        *reinterpret_cast<float4*>(op) = o;
    }
}

extern "C" void kernel_launch(void* const* d_in, const int* in_sizes, int n_in,
                              void* d_out, int out_size) {
    const float* img = (const float*)d_in[0];
    float* out = (float*)d_out;

    dim3 grid(IMG_W / XSPAN, (IMG_H + YTILE - 1) / YTILE, IMG_B);   // 2 x 69 x 16
    k_fused<<<grid, NTHREADS>>>(img, out);
}